// round 15
// baseline (speedup 1.0000x reference)
#include <cuda_runtime.h>
#include <cuda_fp16.h>
#include <cstdint>

// ============================================================================
// 3-layer MLP via mma.sync.m16n8k16.f32.f16.f16.f32 on sm_103a.
//   out = relu(relu(x@w1+b1)@w2+b2)@w3+b3
// CTA 64x256, 256 threads, 8 warps (2Mx4N), warp tile 32x64.
// BM=64 shrinks tile granularity: L1/L2 = 1024 tiles over 152 persistent
// CTAs -> 7 waves vs 6.74 ideal (3.9% quantization loss; was 16% at BM=128).
// BK=64 (two BK=32 sub-stages per step): ONE CP_WAIT+__syncthreads per
// 4096 mma-cycles (verified 1/BK overhead law; 96% of pipe at BK=64).
// 4-stage cp.async ring (160KB smem), persistent CTAs, seamless cross-tile
// prefetch (ktiles%4==0 everywhere).
// K-layout per 32-group: logical k at
//   perm32(k) = 8*(((k&15)>>1)&3) + 4*(k>>4) + 2*((k>>3)&1) + (k&1)
// -> each fragment row is ONE conflict-free lds.128 covering both k16 halves.
// fp16 operands (11-bit mantissa = tf32 class), f32 accumulate; h1/h2 are
// perm32 fp16 in gmem; all conversions round-to-nearest.
// ============================================================================

#define DINL __device__ __forceinline__

constexpr int BATCH = 4096, IN = 2048, HID = 4096, NCLS = 1000, NCLS_PAD = 1024;

constexpr int BM = 64, BN = 256, BK = 64;
constexpr int STAGES = 4;
constexpr int A_HALF = BM * 32 * 2;         // 4096 B  (one 32-wide sub-stage)
constexpr int B_HALF = BN * 32 * 2;         // 16384 B
constexpr int A_ST = 2 * A_HALF;            // 8192 B
constexpr int B_ST = 2 * B_HALF;            // 32768 B
constexpr int B_OFF = STAGES * A_ST;        // 32768
constexpr int SMEM_TOT = STAGES * (A_ST + B_ST);   // 163840 B (160KB)

constexpr int MF = 2, NF = 8;               // warp tile 32 x 64
constexpr int NSM = 152;
constexpr int GRID = NSM;                   // 1 CTA/SM persistent

// device scratch (allocation-guard-safe), fp16 perm32 layouts
__device__ __half g_h1 [(size_t)BATCH * HID];
__device__ __half g_h2 [(size_t)BATCH * HID];
__device__ __half g_xr [(size_t)BATCH * IN];
__device__ __half g_w1t[(size_t)HID * IN];
__device__ __half g_w2t[(size_t)HID * HID];
__device__ __half g_w3t[(size_t)NCLS_PAD * HID];

// ---------------------------------------------------------------- helpers
DINL uint32_t s2u(const void* p) {
    uint32_t a;
    asm("{ .reg .u64 t; cvta.to.shared.u64 t, %1; cvt.u32.u64 %0, t; }"
        : "=r"(a) : "l"(p));
    return a;
}
DINL void cp_async16(uint32_t s, const void* g) {
    asm volatile("cp.async.cg.shared.global [%0], [%1], 16;" :: "r"(s), "l"(g));
}
DINL void cp_commit() { asm volatile("cp.async.commit_group;" ::: "memory"); }
#define CP_WAIT(n) asm volatile("cp.async.wait_group %0;" :: "n"(n) : "memory")

DINL uint4 lds128(uint32_t a) {
    uint4 v;
    asm volatile("ld.shared.v4.b32 {%0,%1,%2,%3}, [%4];"
                 : "=r"(v.x), "=r"(v.y), "=r"(v.z), "=r"(v.w) : "r"(a));
    return v;
}
DINL void mma16816(float* d, uint32_t a0, uint32_t a1, uint32_t a2, uint32_t a3,
                   uint32_t b0, uint32_t b1) {
    asm volatile(
        "mma.sync.aligned.m16n8k16.row.col.f32.f16.f16.f32 "
        "{%0,%1,%2,%3}, {%4,%5,%6,%7}, {%8,%9}, {%0,%1,%2,%3};"
        : "+f"(d[0]), "+f"(d[1]), "+f"(d[2]), "+f"(d[3])
        : "r"(a0), "r"(a1), "r"(a2), "r"(a3), "r"(b0), "r"(b1));
}
// 32-wide K-permutation
DINL int perm32(int j) {
    const int jj = j & 15;
    return 8 * ((jj >> 1) & 3) + 4 * ((j >> 4) & 1) + 2 * ((jj >> 3) & 1) + (jj & 1);
}

// ------------------------------------------------------------------ GEMM
// A [M,K] fp16 row-major (perm32 within 32-groups), Bt [Npad,K] fp16 same,
// Cv: fp16 (perm32, layers 1/2) or f32 plain (layer 3).
// flags: bit0 relu, bit1 fp16-perm32 output (else f32 plain).
__global__ __launch_bounds__(256, 1)
void mlp_gemm_h(const __half* __restrict__ A, const __half* __restrict__ Bt,
                const float* __restrict__ bias, void* __restrict__ Cv,
                int K, int N, int Mt, int Nt, int flags) {
    extern __shared__ char smem[];
    const uint32_t sb = s2u(smem);
    const int tid = threadIdx.x;
    const int wid = tid >> 5, lid = tid & 31;
    const int warp_m = wid & 1;           // 0..1  (32 rows)
    const int warp_n = wid >> 1;          // 0..3  (64 cols)
    const int lg = lid >> 2;              // 0..7
    const int lc = lid & 3;               // 0..3
    const int ktiles = K / BK;
    const int ntile = Mt * Nt;
    const int do_relu = flags & 1, do_h16 = flags & 2;

    int idx = blockIdx.x;
    if (idx >= ntile) return;

    // per-thread load assignment (constant across tiles/kts):
    // per sub-stage: A 256 chunks of 16B (1/thread), B 1024 (4/thread)
    const int ld_row = tid >> 2, ld_j = tid & 3;       // rows 0..63, 16B lane
    const uint32_t a_dst0 = sb + ld_row * 64 + ld_j * 16;
    const uint32_t b_dst0 = sb + B_OFF + ld_row * 64 + ld_j * 16;
    const size_t src0 = (size_t)ld_row * K + ld_j * 8;    // elements

    auto load_stage = [&](const __half* Ag, const __half* Bg, int kt, int buf) {
        const __half* ap = Ag + (size_t)kt * BK;
        const uint32_t ab = a_dst0 + buf * A_ST;
#pragma unroll
        for (int h = 0; h < 2; h++)
            cp_async16(ab + h * A_HALF, ap + src0 + h * 32);
        const __half* bp = Bg + (size_t)kt * BK;
        const uint32_t bb = b_dst0 + buf * B_ST;
#pragma unroll
        for (int h = 0; h < 2; h++)
#pragma unroll
            for (int t = 0; t < 4; t++)
                cp_async16(bb + h * B_HALF + t * 64 * 64,
                           bp + src0 + (size_t)t * 64 * K + h * 32);
    };

    int m0 = (idx % Mt) * BM, n0 = (idx / Mt) * BN;
    const __half* Ag = A + (size_t)m0 * K;
    const __half* Bg = Bt + (size_t)n0 * K;

    for (int s = 0; s < STAGES - 1; s++) { load_stage(Ag, Bg, s, s); cp_commit(); }

    // fragment base byte addrs (buffer 0); sub-stage rows are 64B
    const uint32_t a_t0 = sb + (warp_m * 32 + lg) * 64 + 16 * lc;
    const uint32_t b_t0 = sb + B_OFF + (warp_n * 64 + lg) * 64 + 16 * lc;

    for (;;) {
        const int nidx = idx + GRID;
        const int valid = nidx < ntile;
        const __half* Agn = valid ? A + (size_t)((nidx % Mt) * BM) * K : Ag;
        const __half* Bgn = valid ? Bt + (size_t)((nidx / Mt) * BN) * K : Bg;

        float acc[MF][NF][4];
#pragma unroll
        for (int i = 0; i < MF; i++)
#pragma unroll
            for (int j = 0; j < NF; j++)
#pragma unroll
                for (int r = 0; r < 4; r++) acc[i][j][r] = 0.f;

        for (int kt = 0; kt < ktiles; kt++) {
            const int b = kt & (STAGES - 1);
            CP_WAIT(STAGES - 2);
            __syncthreads();

            const int nk = kt + STAGES - 1;
            if (nk < ktiles)  load_stage(Ag, Bg, nk, nk & (STAGES - 1));
            else if (valid)   load_stage(Agn, Bgn, nk - ktiles, nk & (STAGES - 1));
            cp_commit();

#pragma unroll
            for (int h = 0; h < 2; h++) {
                const uint32_t ab = a_t0 + b * A_ST + h * A_HALF;
                const uint32_t bb = b_t0 + b * B_ST + h * B_HALF;

                // one lds.128 per fragment row covers both k16 groups:
                //   .x={a0,a1} g0  .y={a2,a3} g0  .z,.w same for g1
                uint4 af[MF][2];
#pragma unroll
                for (int mf = 0; mf < MF; mf++) {
                    af[mf][0] = lds128(ab + mf * 1024);        // row lg
                    af[mf][1] = lds128(ab + mf * 1024 + 512);  // row lg+8
                }
                uint4 bf[NF];
#pragma unroll
                for (int nf = 0; nf < NF; nf++)
                    bf[nf] = lds128(bb + nf * 512);            // col lg
#pragma unroll
                for (int mf = 0; mf < MF; mf++)
#pragma unroll
                    for (int nf = 0; nf < NF; nf++) {
                        mma16816(acc[mf][nf], af[mf][0].x, af[mf][1].x,
                                 af[mf][0].y, af[mf][1].y, bf[nf].x, bf[nf].y);
                        mma16816(acc[mf][nf], af[mf][0].z, af[mf][1].z,
                                 af[mf][0].w, af[mf][1].w, bf[nf].z, bf[nf].w);
                    }
            }
        }

        // ---- epilogue (next tile's stages already streaming)
        float bvv[NF][2];
#pragma unroll
        for (int nf = 0; nf < NF; nf++) {
            const int c = n0 + warp_n * 64 + nf * 8 + 2 * lc;
            bvv[nf][0] = (c < N) ? __ldg(bias + c) : 0.f;
            bvv[nf][1] = (c + 1 < N) ? __ldg(bias + c + 1) : 0.f;
        }
#pragma unroll
        for (int mf = 0; mf < MF; mf++) {
#pragma unroll
            for (int r2 = 0; r2 < 2; r2++) {
                const int m = m0 + warp_m * 32 + mf * 16 + lg + r2 * 8;
#pragma unroll
                for (int nf = 0; nf < NF; nf++) {
                    const int c = n0 + warp_n * 64 + nf * 8 + 2 * lc;
                    float v0 = acc[mf][nf][r2 * 2 + 0] + bvv[nf][0];
                    float v1 = acc[mf][nf][r2 * 2 + 1] + bvv[nf][1];
                    if (do_relu) { v0 = fmaxf(v0, 0.f); v1 = fmaxf(v1, 0.f); }
                    if (do_h16) {
                        // perm32 slot of logical pair (c,c+1):
                        // phys = 8*lc + 4*((nf>>1)&1) + 2*(nf&1)
                        __half* crow = (__half*)Cv + (size_t)m * N;
                        const int pidx = (c & ~31) + 8 * lc +
                                         4 * ((nf >> 1) & 1) + 2 * (nf & 1);
                        *(__half2*)(crow + pidx) = __floats2half2_rn(v0, v1);
                    } else if (c < N) {
                        float* crow = (float*)Cv + (size_t)m * N;
                        *(float2*)(crow + c) = make_float2(v0, v1);
                    }
                }
            }
        }

        if (!valid) break;
        idx = nidx;
        m0 = (idx % Mt) * BM; n0 = (idx / Mt) * BN;
        Ag = Agn; Bg = Bgn;
    }
}

// ---------------------------------------------------- fused prep (1 launch)
__device__ void transpose_job(const float* __restrict__ s, __half* __restrict__ d,
                              int R, int C, int bx, int by) {
    __shared__ float t[32][33];
    const int tid = threadIdx.x;
    const int x = tid & 31, y = tid >> 5;   // 32 x 8
    const int c0 = bx * 32, r0 = by * 32;
#pragma unroll
    for (int i = y; i < 32; i += 8) {
        int r = r0 + i, c = c0 + x;
        t[i][x] = (c < C) ? s[(size_t)r * C + c] : 0.f;
    }
    __syncthreads();
#pragma unroll
    for (int i = y; i < 32; i += 8) {
        int cc = c0 + i, rr = r0 + x;        // cc = out row (N), rr = K pos
        int rp = (rr & ~31) | perm32(rr & 31);
        d[(size_t)cc * R + rp] = __float2half_rn(t[x][i]);
    }
}

constexpr int G_W1 = (HID / 32) * (IN / 32);        // 8192
constexpr int G_W2 = (HID / 32) * (HID / 32);       // 16384
constexpr int G_W3 = (NCLS_PAD / 32) * (HID / 32);  // 4096
constexpr int G_X  = (BATCH * IN) / 8192;           // 1024 (32 floats/thread)
constexpr int G_PREP = G_W1 + G_W2 + G_W3 + G_X;

__global__ __launch_bounds__(256)
void prep_all(const float* __restrict__ w1, const float* __restrict__ w2,
              const float* __restrict__ w3, const float* __restrict__ x,
              __half* __restrict__ w1t, __half* __restrict__ w2t,
              __half* __restrict__ w3t, __half* __restrict__ xr) {
    int id = blockIdx.x;
    if (id < G_W1) {
        transpose_job(w1, w1t, IN, HID, id % (HID / 32), id / (HID / 32));
        return;
    }
    id -= G_W1;
    if (id < G_W2) {
        transpose_job(w2, w2t, HID, HID, id % (HID / 32), id / (HID / 32));
        return;
    }
    id -= G_W2;
    if (id < G_W3) {
        transpose_job(w3, w3t, HID, NCLS, id % (NCLS_PAD / 32), id / (NCLS_PAD / 32));
        return;
    }
    id -= G_W3;
    // x: fp16-convert + perm32; 32 floats/thread (one 32-group)
    const size_t base = (size_t)id * 8192 + threadIdx.x * 32;
    float f[32];
#pragma unroll
    for (int i = 0; i < 32; i += 4) *(float4*)&f[i] = *(const float4*)(x + base + i);
    __half h[32];
#pragma unroll
    for (int j = 0; j < 32; j++) h[perm32(j)] = __float2half_rn(f[j]);
#pragma unroll
    for (int i = 0; i < 4; i++)
        *(uint4*)(xr + base + i * 8) = *(uint4*)&h[i * 8];
}

// ----------------------------------------------------------------- launcher
extern "C" void kernel_launch(void* const* d_in, const int* in_sizes, int n_in,
                              void* d_out, int out_size) {
    (void)in_sizes; (void)n_in; (void)out_size;
    const float* x  = (const float*)d_in[0];
    const float* w1 = (const float*)d_in[1];
    const float* b1 = (const float*)d_in[2];
    const float* w2 = (const float*)d_in[3];
    const float* b2 = (const float*)d_in[4];
    const float* w3 = (const float*)d_in[5];
    const float* b3 = (const float*)d_in[6];

    __half *h1, *h2, *xr, *w1t, *w2t, *w3t;
    cudaGetSymbolAddress((void**)&h1,  g_h1);
    cudaGetSymbolAddress((void**)&h2,  g_h2);
    cudaGetSymbolAddress((void**)&xr,  g_xr);
    cudaGetSymbolAddress((void**)&w1t, g_w1t);
    cudaGetSymbolAddress((void**)&w2t, g_w2t);
    cudaGetSymbolAddress((void**)&w3t, g_w3t);

    cudaFuncSetAttribute(mlp_gemm_h,
                         cudaFuncAttributeMaxDynamicSharedMemorySize, SMEM_TOT);

    prep_all<<<G_PREP, 256>>>(w1, w2, w3, x, w1t, w2t, w3t, xr);

    const int MT = BATCH / BM;                 // 64
    mlp_gemm_h<<<GRID, 256, SMEM_TOT>>>(
        xr, w1t, b1, h1, IN, HID, MT, HID / BN, /*relu|h16*/ 3);
    mlp_gemm_h<<<GRID, 256, SMEM_TOT>>>(
        h1, w2t, b2, h2, HID, HID, MT, HID / BN, 3);
    mlp_gemm_h<<<GRID, 256, SMEM_TOT>>>(
        h2, w3t, b3, d_out, HID, NCLS, MT, NCLS_PAD / BN, 0);
}

// round 16
// speedup vs baseline: 1.1618x; 1.1618x over previous
#include <cuda_runtime.h>
#include <cuda_fp16.h>
#include <cstdint>

// ============================================================================
// 3-layer MLP via mma.sync.m16n8k16.f32.f16.f16.f32 on sm_103a.
//   out = relu(relu(x@w1+b1)@w2+b2)@w3+b3
// Engine (round-14, 96% of half-rate HMMA pipe): CTA 128x256, 256 threads,
// 8 warps (2Mx4N), warp tile 64x64, BK=64 (two BK=32 sub-stages per step,
// ONE CP_WAIT+__syncthreads per 4096 mma-cycles), 4-stage cp.async ring,
// persistent CTAs with seamless cross-tile prefetch.
// NEW: wave-quantization fix. L1/L2 (512 tiles = 3.37 waves of 152) are
// split into a main launch of 456 tiles (EXACTLY 3 full waves) plus a
// remainder launch covering tiles 456..511 as 112 N-half tiles (128x128,
// template BN=128) on grid 112 -- a half-duration 4th wave. 3.5 eff. waves
// instead of 4. Per-kt work per CTA stays >= 2048 mma-cyc everywhere.
// K-layout per 32-group: logical k at
//   perm32(k) = 8*(((k&15)>>1)&3) + 4*(k>>4) + 2*((k>>3)&1) + (k&1)
// -> each fragment row is ONE conflict-free lds.128 covering both k16 halves.
// fp16 operands (11-bit mantissa = tf32 class), f32 accumulate; h1/h2 are
// perm32 fp16 in gmem; all conversions round-to-nearest.
// ============================================================================

#define DINL __device__ __forceinline__

constexpr int BATCH = 4096, IN = 2048, HID = 4096, NCLS = 1000, NCLS_PAD = 1024;

constexpr int BM = 128, BK = 64;
constexpr int STAGES = 4;
constexpr int A_HALF = BM * 32 * 2;         // 8192 B (one 32-wide sub-stage)
constexpr int A_ST = 2 * A_HALF;            // 16384 B
constexpr int B_OFF = STAGES * A_ST;        // 65536
constexpr int MF = 4;                       // warp tile M = 64 (2 warps in M)
constexpr int NSM = 152;

// device scratch (allocation-guard-safe), fp16 perm32 layouts
__device__ __half g_h1 [(size_t)BATCH * HID];
__device__ __half g_h2 [(size_t)BATCH * HID];
__device__ __half g_xr [(size_t)BATCH * IN];
__device__ __half g_w1t[(size_t)HID * IN];
__device__ __half g_w2t[(size_t)HID * HID];
__device__ __half g_w3t[(size_t)NCLS_PAD * HID];

// ---------------------------------------------------------------- helpers
DINL uint32_t s2u(const void* p) {
    uint32_t a;
    asm("{ .reg .u64 t; cvta.to.shared.u64 t, %1; cvt.u32.u64 %0, t; }"
        : "=r"(a) : "l"(p));
    return a;
}
DINL void cp_async16(uint32_t s, const void* g) {
    asm volatile("cp.async.cg.shared.global [%0], [%1], 16;" :: "r"(s), "l"(g));
}
DINL void cp_commit() { asm volatile("cp.async.commit_group;" ::: "memory"); }
#define CP_WAIT(n) asm volatile("cp.async.wait_group %0;" :: "n"(n) : "memory")

DINL uint4 lds128(uint32_t a) {
    uint4 v;
    asm volatile("ld.shared.v4.b32 {%0,%1,%2,%3}, [%4];"
                 : "=r"(v.x), "=r"(v.y), "=r"(v.z), "=r"(v.w) : "r"(a));
    return v;
}
DINL void mma16816(float* d, uint32_t a0, uint32_t a1, uint32_t a2, uint32_t a3,
                   uint32_t b0, uint32_t b1) {
    asm volatile(
        "mma.sync.aligned.m16n8k16.row.col.f32.f16.f16.f32 "
        "{%0,%1,%2,%3}, {%4,%5,%6,%7}, {%8,%9}, {%0,%1,%2,%3};"
        : "+f"(d[0]), "+f"(d[1]), "+f"(d[2]), "+f"(d[3])
        : "r"(a0), "r"(a1), "r"(a2), "r"(a3), "r"(b0), "r"(b1));
}
// 32-wide K-permutation
DINL int perm32(int j) {
    const int jj = j & 15;
    return 8 * ((jj >> 1) & 3) + 4 * ((j >> 4) & 1) + 2 * ((jj >> 3) & 1) + (jj & 1);
}

// ------------------------------------------------------------------ GEMM
// Template TBN: 256 = full tiles (units ARE tiles, N offset = t/Mt*256);
//               128 = N-half tiles (unit u -> tile tile_base+u/2, half u&1).
// A [M,K] fp16 row-major (perm32 in 32-groups), Bt [Npad,K] fp16 same,
// Cv: fp16 (perm32, layers 1/2) or f32 plain (layer 3).
// flags: bit0 relu, bit1 fp16-perm32 output (else f32 plain).
template <int TBN>
__global__ __launch_bounds__(256, 1)
void mlp_gemm_h(const __half* __restrict__ A, const __half* __restrict__ Bt,
                const float* __restrict__ bias, void* __restrict__ Cv,
                int K, int N, int Mt, int nunits, int tile_base, int flags) {
    constexpr int NF = TBN / 32;            // warp tile N = TBN/4
    constexpr int WN = TBN / 4;
    constexpr int B_HALF = TBN * 32 * 2;
    constexpr int B_ST = 2 * B_HALF;

    extern __shared__ char smem[];
    const uint32_t sb = s2u(smem);
    const int tid = threadIdx.x;
    const int wid = tid >> 5, lid = tid & 31;
    const int warp_m = wid & 1;           // 0..1  (64 rows)
    const int warp_n = wid >> 1;          // 0..3  (WN cols)
    const int lg = lid >> 2;              // 0..7
    const int lc = lid & 3;               // 0..3
    const int ktiles = K / BK;
    const int do_relu = flags & 1, do_h16 = flags & 2;

    auto map_unit = [&](int u, int& m0, int& n0) {
        if (TBN == 256) {
            const int t = tile_base + u;
            m0 = (t % Mt) * BM; n0 = (t / Mt) * 256;
        } else {
            const int t = tile_base + (u >> 1);
            m0 = (t % Mt) * BM; n0 = (t / Mt) * 256 + (u & 1) * 128;
        }
    };

    int idx = blockIdx.x;
    if (idx >= nunits) return;

    // per-thread load assignment (constant across tiles/kts)
    const int ld_row = tid >> 2, ld_j = tid & 3;       // rows 0..63, 16B lane
    const uint32_t a_dst0 = sb + ld_row * 64 + ld_j * 16;
    const uint32_t b_dst0 = sb + B_OFF + ld_row * 64 + ld_j * 16;
    const size_t src0 = (size_t)ld_row * K + ld_j * 8;    // elements

    auto load_stage = [&](const __half* Ag, const __half* Bg, int kt, int buf) {
        const __half* ap = Ag + (size_t)kt * BK;
        const uint32_t ab = a_dst0 + buf * A_ST;
#pragma unroll
        for (int h = 0; h < 2; h++)
#pragma unroll
            for (int t = 0; t < 2; t++)     // 128 A rows
                cp_async16(ab + h * A_HALF + t * 64 * 64,
                           ap + src0 + (size_t)t * 64 * K + h * 32);
        const __half* bp = Bg + (size_t)kt * BK;
        const uint32_t bb = b_dst0 + buf * B_ST;
#pragma unroll
        for (int h = 0; h < 2; h++)
#pragma unroll
            for (int t = 0; t < TBN / 64; t++)   // TBN B rows
                cp_async16(bb + h * B_HALF + t * 64 * 64,
                           bp + src0 + (size_t)t * 64 * K + h * 32);
    };

    int m0, n0;
    map_unit(idx, m0, n0);
    const __half* Ag = A + (size_t)m0 * K;
    const __half* Bg = Bt + (size_t)n0 * K;

    for (int s = 0; s < STAGES - 1; s++) { load_stage(Ag, Bg, s, s); cp_commit(); }

    // fragment base byte addrs (buffer 0); sub-stage rows are 64B
    const uint32_t a_t0 = sb + (warp_m * 64 + lg) * 64 + 16 * lc;
    const uint32_t b_t0 = sb + B_OFF + (warp_n * WN + lg) * 64 + 16 * lc;

    for (;;) {
        const int nidx = idx + (int)gridDim.x;
        const int valid = nidx < nunits;
        int m0n = m0, n0n = n0;
        if (valid) map_unit(nidx, m0n, n0n);
        const __half* Agn = A + (size_t)m0n * K;
        const __half* Bgn = Bt + (size_t)n0n * K;

        float acc[MF][NF][4];
#pragma unroll
        for (int i = 0; i < MF; i++)
#pragma unroll
            for (int j = 0; j < NF; j++)
#pragma unroll
                for (int r = 0; r < 4; r++) acc[i][j][r] = 0.f;

        for (int kt = 0; kt < ktiles; kt++) {
            const int b = kt & (STAGES - 1);
            CP_WAIT(STAGES - 2);
            __syncthreads();

            const int nk = kt + STAGES - 1;
            if (nk < ktiles)  load_stage(Ag, Bg, nk, nk & (STAGES - 1));
            else if (valid)   load_stage(Agn, Bgn, nk - ktiles, nk & (STAGES - 1));
            cp_commit();

#pragma unroll
            for (int h = 0; h < 2; h++) {
                const uint32_t ab = a_t0 + b * A_ST + h * A_HALF;
                const uint32_t bb = b_t0 + b * B_ST + h * B_HALF;

                // one lds.128 per fragment row covers both k16 groups:
                //   .x={a0,a1} g0  .y={a2,a3} g0  .z,.w same for g1
                uint4 af[MF][2];
#pragma unroll
                for (int mf = 0; mf < MF; mf++) {
                    af[mf][0] = lds128(ab + mf * 1024);        // row lg
                    af[mf][1] = lds128(ab + mf * 1024 + 512);  // row lg+8
                }
                uint4 bf[NF];
#pragma unroll
                for (int nf = 0; nf < NF; nf++)
                    bf[nf] = lds128(bb + nf * 512);            // col lg
#pragma unroll
                for (int mf = 0; mf < MF; mf++)
#pragma unroll
                    for (int nf = 0; nf < NF; nf++) {
                        mma16816(acc[mf][nf], af[mf][0].x, af[mf][1].x,
                                 af[mf][0].y, af[mf][1].y, bf[nf].x, bf[nf].y);
                        mma16816(acc[mf][nf], af[mf][0].z, af[mf][1].z,
                                 af[mf][0].w, af[mf][1].w, bf[nf].z, bf[nf].w);
                    }
            }
        }

        // ---- epilogue (next tile's stages already streaming)
        float bvv[NF][2];
#pragma unroll
        for (int nf = 0; nf < NF; nf++) {
            const int c = n0 + warp_n * WN + nf * 8 + 2 * lc;
            bvv[nf][0] = (c < N) ? __ldg(bias + c) : 0.f;
            bvv[nf][1] = (c + 1 < N) ? __ldg(bias + c + 1) : 0.f;
        }
#pragma unroll
        for (int mf = 0; mf < MF; mf++) {
#pragma unroll
            for (int r2 = 0; r2 < 2; r2++) {
                const int m = m0 + warp_m * 64 + mf * 16 + lg + r2 * 8;
#pragma unroll
                for (int nf = 0; nf < NF; nf++) {
                    const int c = n0 + warp_n * WN + nf * 8 + 2 * lc;
                    float v0 = acc[mf][nf][r2 * 2 + 0] + bvv[nf][0];
                    float v1 = acc[mf][nf][r2 * 2 + 1] + bvv[nf][1];
                    if (do_relu) { v0 = fmaxf(v0, 0.f); v1 = fmaxf(v1, 0.f); }
                    if (do_h16) {
                        // perm32 slot of logical pair (c,c+1):
                        // offset-in-32-group = 8*(nf&3)+2*lc ->
                        // phys = 8*lc + 4*((nf>>1)&1) + 2*(nf&1)
                        __half* crow = (__half*)Cv + (size_t)m * N;
                        const int pidx = (c & ~31) + 8 * lc +
                                         4 * ((nf >> 1) & 1) + 2 * (nf & 1);
                        *(__half2*)(crow + pidx) = __floats2half2_rn(v0, v1);
                    } else if (c < N) {
                        float* crow = (float*)Cv + (size_t)m * N;
                        *(float2*)(crow + c) = make_float2(v0, v1);
                    }
                }
            }
        }

        if (!valid) break;
        idx = nidx;
        m0 = m0n; n0 = n0n;
        Ag = Agn; Bg = Bgn;
    }
}

// ---------------------------------------------------- fused prep (1 launch)
__device__ void transpose_job(const float* __restrict__ s, __half* __restrict__ d,
                              int R, int C, int bx, int by) {
    __shared__ float t[32][33];
    const int tid = threadIdx.x;
    const int x = tid & 31, y = tid >> 5;   // 32 x 8
    const int c0 = bx * 32, r0 = by * 32;
#pragma unroll
    for (int i = y; i < 32; i += 8) {
        int r = r0 + i, c = c0 + x;
        t[i][x] = (c < C) ? s[(size_t)r * C + c] : 0.f;
    }
    __syncthreads();
#pragma unroll
    for (int i = y; i < 32; i += 8) {
        int cc = c0 + i, rr = r0 + x;        // cc = out row (N), rr = K pos
        int rp = (rr & ~31) | perm32(rr & 31);
        d[(size_t)cc * R + rp] = __float2half_rn(t[x][i]);
    }
}

constexpr int G_W1 = (HID / 32) * (IN / 32);        // 8192
constexpr int G_W2 = (HID / 32) * (HID / 32);       // 16384
constexpr int G_W3 = (NCLS_PAD / 32) * (HID / 32);  // 4096
constexpr int G_X  = (BATCH * IN) / 8192;           // 1024 (32 floats/thread)
constexpr int G_PREP = G_W1 + G_W2 + G_W3 + G_X;

__global__ __launch_bounds__(256)
void prep_all(const float* __restrict__ w1, const float* __restrict__ w2,
              const float* __restrict__ w3, const float* __restrict__ x,
              __half* __restrict__ w1t, __half* __restrict__ w2t,
              __half* __restrict__ w3t, __half* __restrict__ xr) {
    int id = blockIdx.x;
    if (id < G_W1) {
        transpose_job(w1, w1t, IN, HID, id % (HID / 32), id / (HID / 32));
        return;
    }
    id -= G_W1;
    if (id < G_W2) {
        transpose_job(w2, w2t, HID, HID, id % (HID / 32), id / (HID / 32));
        return;
    }
    id -= G_W2;
    if (id < G_W3) {
        transpose_job(w3, w3t, HID, NCLS, id % (NCLS_PAD / 32), id / (NCLS_PAD / 32));
        return;
    }
    id -= G_W3;
    // x: fp16-convert + perm32; 32 floats/thread (one 32-group)
    const size_t base = (size_t)id * 8192 + threadIdx.x * 32;
    float f[32];
#pragma unroll
    for (int i = 0; i < 32; i += 4) *(float4*)&f[i] = *(const float4*)(x + base + i);
    __half h[32];
#pragma unroll
    for (int j = 0; j < 32; j++) h[perm32(j)] = __float2half_rn(f[j]);
#pragma unroll
    for (int i = 0; i < 4; i++)
        *(uint4*)(xr + base + i * 8) = *(uint4*)&h[i * 8];
}

// ----------------------------------------------------------------- launcher
extern "C" void kernel_launch(void* const* d_in, const int* in_sizes, int n_in,
                              void* d_out, int out_size) {
    (void)in_sizes; (void)n_in; (void)out_size;
    const float* x  = (const float*)d_in[0];
    const float* w1 = (const float*)d_in[1];
    const float* b1 = (const float*)d_in[2];
    const float* w2 = (const float*)d_in[3];
    const float* b2 = (const float*)d_in[4];
    const float* w3 = (const float*)d_in[5];
    const float* b3 = (const float*)d_in[6];

    __half *h1, *h2, *xr, *w1t, *w2t, *w3t;
    cudaGetSymbolAddress((void**)&h1,  g_h1);
    cudaGetSymbolAddress((void**)&h2,  g_h2);
    cudaGetSymbolAddress((void**)&xr,  g_xr);
    cudaGetSymbolAddress((void**)&w1t, g_w1t);
    cudaGetSymbolAddress((void**)&w2t, g_w2t);
    cudaGetSymbolAddress((void**)&w3t, g_w3t);

    constexpr int SM256 = STAGES * (A_ST + 2 * 256 * 32 * 2);   // 196608
    constexpr int SM128 = STAGES * (A_ST + 2 * 128 * 32 * 2);   // 131072
    cudaFuncSetAttribute(mlp_gemm_h<256>,
                         cudaFuncAttributeMaxDynamicSharedMemorySize, SM256);
    cudaFuncSetAttribute(mlp_gemm_h<128>,
                         cudaFuncAttributeMaxDynamicSharedMemorySize, SM128);

    prep_all<<<G_PREP, 256>>>(w1, w2, w3, x, w1t, w2t, w3t, xr);

    const int MT = BATCH / BM;                     // 32
    const int MAIN = 3 * NSM;                      // 456 tiles = 3 exact waves
    const int REM_T = 512 - MAIN;                  // 56 tiles
    const int REM_U = 2 * REM_T;                   // 112 half-tiles

    // layer 1 (K=2048): main 3 waves + half-width remainder wave
    mlp_gemm_h<256><<<NSM, 256, SM256>>>(
        xr, w1t, b1, h1, IN, HID, MT, MAIN, 0, /*relu|h16*/ 3);
    mlp_gemm_h<128><<<REM_U, 256, SM128>>>(
        xr, w1t, b1, h1, IN, HID, MT, REM_U, MAIN, 3);

    // layer 2 (K=4096)
    mlp_gemm_h<256><<<NSM, 256, SM256>>>(
        h1, w2t, b2, h2, HID, HID, MT, MAIN, 0, 3);
    mlp_gemm_h<128><<<REM_U, 256, SM128>>>(
        h1, w2t, b2, h2, HID, HID, MT, REM_U, MAIN, 3);

    // layer 3 (128 tiles, single wave)
    mlp_gemm_h<256><<<NSM, 256, SM256>>>(
        h2, w3t, b3, d_out, HID, NCLS, MT, 128, 0, 0);
}

// round 17
// speedup vs baseline: 1.1920x; 1.0260x over previous
#include <cuda_runtime.h>
#include <cuda_fp16.h>
#include <cstdint>

// ============================================================================
// 3-layer MLP via mma.sync.m16n8k16.f32.f16.f16.f32 on sm_103a.
//   out = relu(relu(x@w1+b1)@w2+b2)@w3+b3
// Engine: CTA 128x256, 256 threads, 8 warps (2Mx4N), warp tile 64x64.
// BK=128 (four 32-wide sub-stages per step): ONE CP_WAIT+__syncthreads per
// ~4096 mma-busy cycles. Measured idle ladder (BK 16/32/64 -> tensor
// 37/44/57%) has a large fixed-per-kt component -- BK=128 amortizes it 2x.
// 2-stage double buffer (192KB smem): wait-all -> sync -> compute 4 subs,
// with the next stage's cp.asyncs issued after sub-stage 0 (post-barrier
// critical path goes straight to LDS->mma; slack ~1 full stage >> DRAM lat).
// Wave-quantization fix (round 16): L1/L2 (512 tiles = 3.37 waves) run as
// a main launch of 456 tiles (3 exact waves) + a remainder launch of 112
// N-half tiles (128x128) -- a half-duration 4th wave.
// K-layout per 32-group: logical k at
//   perm32(k) = 8*(((k&15)>>1)&3) + 4*(k>>4) + 2*((k>>3)&1) + (k&1)
// -> each fragment row is ONE conflict-free lds.128 covering both k16 halves.
// fp16 operands (11-bit mantissa = tf32 class), f32 accumulate; h1/h2 are
// perm32 fp16 in gmem; all conversions round-to-nearest.
// ============================================================================

#define DINL __device__ __forceinline__

constexpr int BATCH = 4096, IN = 2048, HID = 4096, NCLS = 1000, NCLS_PAD = 1024;

constexpr int BM = 128, BK = 128;
constexpr int STAGES = 2;
constexpr int NSUB = 4;                     // 32-wide sub-stages per kt
constexpr int A_SUB = BM * 32 * 2;          // 8192 B
constexpr int A_ST = NSUB * A_SUB;          // 32768 B
constexpr int B_OFF = STAGES * A_ST;        // 65536
constexpr int MF = 4;                       // warp tile M = 64
constexpr int NSM = 152;

// device scratch (allocation-guard-safe), fp16 perm32 layouts
__device__ __half g_h1 [(size_t)BATCH * HID];
__device__ __half g_h2 [(size_t)BATCH * HID];
__device__ __half g_xr [(size_t)BATCH * IN];
__device__ __half g_w1t[(size_t)HID * IN];
__device__ __half g_w2t[(size_t)HID * HID];
__device__ __half g_w3t[(size_t)NCLS_PAD * HID];

// ---------------------------------------------------------------- helpers
DINL uint32_t s2u(const void* p) {
    uint32_t a;
    asm("{ .reg .u64 t; cvta.to.shared.u64 t, %1; cvt.u32.u64 %0, t; }"
        : "=r"(a) : "l"(p));
    return a;
}
DINL void cp_async16(uint32_t s, const void* g) {
    asm volatile("cp.async.cg.shared.global [%0], [%1], 16;" :: "r"(s), "l"(g));
}
DINL void cp_commit() { asm volatile("cp.async.commit_group;" ::: "memory"); }
#define CP_WAIT_ALL() asm volatile("cp.async.wait_group 0;" ::: "memory")

DINL uint4 lds128(uint32_t a) {
    uint4 v;
    asm volatile("ld.shared.v4.b32 {%0,%1,%2,%3}, [%4];"
                 : "=r"(v.x), "=r"(v.y), "=r"(v.z), "=r"(v.w) : "r"(a));
    return v;
}
DINL void mma16816(float* d, uint32_t a0, uint32_t a1, uint32_t a2, uint32_t a3,
                   uint32_t b0, uint32_t b1) {
    asm volatile(
        "mma.sync.aligned.m16n8k16.row.col.f32.f16.f16.f32 "
        "{%0,%1,%2,%3}, {%4,%5,%6,%7}, {%8,%9}, {%0,%1,%2,%3};"
        : "+f"(d[0]), "+f"(d[1]), "+f"(d[2]), "+f"(d[3])
        : "r"(a0), "r"(a1), "r"(a2), "r"(a3), "r"(b0), "r"(b1));
}
// 32-wide K-permutation
DINL int perm32(int j) {
    const int jj = j & 15;
    return 8 * ((jj >> 1) & 3) + 4 * ((j >> 4) & 1) + 2 * ((jj >> 3) & 1) + (jj & 1);
}

// ------------------------------------------------------------------ GEMM
// Template TBN: 256 = full tiles; 128 = N-half tiles (remainder wave).
// A [M,K] fp16 row-major (perm32 in 32-groups), Bt [Npad,K] fp16 same,
// Cv: fp16 (perm32, layers 1/2) or f32 plain (layer 3).
// flags: bit0 relu, bit1 fp16-perm32 output (else f32 plain).
template <int TBN>
__global__ __launch_bounds__(256, 1)
void mlp_gemm_h(const __half* __restrict__ A, const __half* __restrict__ Bt,
                const float* __restrict__ bias, void* __restrict__ Cv,
                int K, int N, int Mt, int nunits, int tile_base, int flags) {
    constexpr int NF = TBN / 32;            // warp tile N = TBN/4
    constexpr int WN = TBN / 4;
    constexpr int B_SUB = TBN * 32 * 2;
    constexpr int B_ST = NSUB * B_SUB;

    extern __shared__ char smem[];
    const uint32_t sb = s2u(smem);
    const int tid = threadIdx.x;
    const int wid = tid >> 5, lid = tid & 31;
    const int warp_m = wid & 1;           // 0..1  (64 rows)
    const int warp_n = wid >> 1;          // 0..3  (WN cols)
    const int lg = lid >> 2;              // 0..7
    const int lc = lid & 3;               // 0..3
    const int ktiles = K / BK;
    const int do_relu = flags & 1, do_h16 = flags & 2;

    auto map_unit = [&](int u, int& m0, int& n0) {
        if (TBN == 256) {
            const int t = tile_base + u;
            m0 = (t % Mt) * BM; n0 = (t / Mt) * 256;
        } else {
            const int t = tile_base + (u >> 1);
            m0 = (t % Mt) * BM; n0 = (t / Mt) * 256 + (u & 1) * 128;
        }
    };

    int idx = blockIdx.x;
    if (idx >= nunits) return;

    // per-thread load assignment (constant across tiles/kts)
    const int ld_row = tid >> 2, ld_j = tid & 3;       // rows 0..63, 16B lane
    const uint32_t a_dst0 = sb + ld_row * 64 + ld_j * 16;
    const uint32_t b_dst0 = sb + B_OFF + ld_row * 64 + ld_j * 16;
    const size_t src0 = (size_t)ld_row * K + ld_j * 8;    // elements

    auto load_stage = [&](const __half* Ag, const __half* Bg, int kt, int buf) {
        const __half* ap = Ag + (size_t)kt * BK;
        const uint32_t ab = a_dst0 + buf * A_ST;
#pragma unroll
        for (int h = 0; h < NSUB; h++)
#pragma unroll
            for (int t = 0; t < 2; t++)     // 128 A rows
                cp_async16(ab + h * A_SUB + t * 64 * 64,
                           ap + src0 + (size_t)t * 64 * K + h * 32);
        const __half* bp = Bg + (size_t)kt * BK;
        const uint32_t bb = b_dst0 + buf * B_ST;
#pragma unroll
        for (int h = 0; h < NSUB; h++)
#pragma unroll
            for (int t = 0; t < TBN / 64; t++)   // TBN B rows
                cp_async16(bb + h * B_SUB + t * 64 * 64,
                           bp + src0 + (size_t)t * 64 * K + h * 32);
        cp_commit();
    };

    int m0, n0;
    map_unit(idx, m0, n0);
    const __half* Ag = A + (size_t)m0 * K;
    const __half* Bg = Bt + (size_t)n0 * K;

    load_stage(Ag, Bg, 0, 0);               // prologue: stage 0

    // fragment base byte addrs (buffer 0); sub-stage rows are 64B
    const uint32_t a_t0 = sb + (warp_m * 64 + lg) * 64 + 16 * lc;
    const uint32_t b_t0 = sb + B_OFF + (warp_n * WN + lg) * 64 + 16 * lc;

    for (;;) {
        const int nidx = idx + (int)gridDim.x;
        const int valid = nidx < nunits;
        int m0n = m0, n0n = n0;
        if (valid) map_unit(nidx, m0n, n0n);
        const __half* Agn = A + (size_t)m0n * K;
        const __half* Bgn = Bt + (size_t)n0n * K;

        float acc[MF][NF][4];
#pragma unroll
        for (int i = 0; i < MF; i++)
#pragma unroll
            for (int j = 0; j < NF; j++)
#pragma unroll
                for (int r = 0; r < 4; r++) acc[i][j][r] = 0.f;

        for (int kt = 0; kt < ktiles; kt++) {
            const int b = kt & 1;
            CP_WAIT_ALL();
            __syncthreads();

#pragma unroll
            for (int h = 0; h < NSUB; h++) {
                const uint32_t ab = a_t0 + b * A_ST + h * A_SUB;
                const uint32_t bb = b_t0 + b * B_ST + h * B_SUB;

                // one lds.128 per fragment row covers both k16 groups:
                //   .x={a0,a1} g0  .y={a2,a3} g0  .z,.w same for g1
                uint4 af[MF][2];
#pragma unroll
                for (int mf = 0; mf < MF; mf++) {
                    af[mf][0] = lds128(ab + mf * 1024);        // row lg
                    af[mf][1] = lds128(ab + mf * 1024 + 512);  // row lg+8
                }
                uint4 bf[NF];
#pragma unroll
                for (int nf = 0; nf < NF; nf++)
                    bf[nf] = lds128(bb + nf * 512);            // col lg
#pragma unroll
                for (int mf = 0; mf < MF; mf++)
#pragma unroll
                    for (int nf = 0; nf < NF; nf++) {
                        mma16816(acc[mf][nf], af[mf][0].x, af[mf][1].x,
                                 af[mf][0].y, af[mf][1].y, bf[nf].x, bf[nf].y);
                        mma16816(acc[mf][nf], af[mf][0].z, af[mf][1].z,
                                 af[mf][0].w, af[mf][1].w, bf[nf].z, bf[nf].w);
                    }

                // issue next stage's loads AFTER the first sub-stage so the
                // post-barrier critical path goes straight into LDS->mma;
                // remaining slack (~3 sub-stages) >> gmem latency.
                if (h == 0) {
                    const int nk = kt + 1;
                    if (nk < ktiles)  load_stage(Ag, Bg, nk, nk & 1);
                    else if (valid)   load_stage(Agn, Bgn, 0, nk & 1);
                }
            }
        }

        // ---- epilogue (next tile's stage already streaming)
        float bvv[NF][2];
#pragma unroll
        for (int nf = 0; nf < NF; nf++) {
            const int c = n0 + warp_n * WN + nf * 8 + 2 * lc;
            bvv[nf][0] = (c < N) ? __ldg(bias + c) : 0.f;
            bvv[nf][1] = (c + 1 < N) ? __ldg(bias + c + 1) : 0.f;
        }
#pragma unroll
        for (int mf = 0; mf < MF; mf++) {
#pragma unroll
            for (int r2 = 0; r2 < 2; r2++) {
                const int m = m0 + warp_m * 64 + mf * 16 + lg + r2 * 8;
#pragma unroll
                for (int nf = 0; nf < NF; nf++) {
                    const int c = n0 + warp_n * WN + nf * 8 + 2 * lc;
                    float v0 = acc[mf][nf][r2 * 2 + 0] + bvv[nf][0];
                    float v1 = acc[mf][nf][r2 * 2 + 1] + bvv[nf][1];
                    if (do_relu) { v0 = fmaxf(v0, 0.f); v1 = fmaxf(v1, 0.f); }
                    if (do_h16) {
                        // perm32 slot of logical even pair (c,c+1)
                        __half* crow = (__half*)Cv + (size_t)m * N;
                        const int pidx = (c & ~31) + perm32(c & 31);
                        *(__half2*)(crow + pidx) = __floats2half2_rn(v0, v1);
                    } else if (c < N) {
                        float* crow = (float*)Cv + (size_t)m * N;
                        *(float2*)(crow + c) = make_float2(v0, v1);
                    }
                }
            }
        }

        if (!valid) break;
        idx = nidx;
        m0 = m0n; n0 = n0n;
        Ag = Agn; Bg = Bgn;
    }
}

// ---------------------------------------------------- fused prep (1 launch)
__device__ void transpose_job(const float* __restrict__ s, __half* __restrict__ d,
                              int R, int C, int bx, int by) {
    __shared__ float t[32][33];
    const int tid = threadIdx.x;
    const int x = tid & 31, y = tid >> 5;   // 32 x 8
    const int c0 = bx * 32, r0 = by * 32;
#pragma unroll
    for (int i = y; i < 32; i += 8) {
        int r = r0 + i, c = c0 + x;
        t[i][x] = (c < C) ? s[(size_t)r * C + c] : 0.f;
    }
    __syncthreads();
#pragma unroll
    for (int i = y; i < 32; i += 8) {
        int cc = c0 + i, rr = r0 + x;        // cc = out row (N), rr = K pos
        int rp = (rr & ~31) | perm32(rr & 31);
        d[(size_t)cc * R + rp] = __float2half_rn(t[x][i]);
    }
}

constexpr int G_W1 = (HID / 32) * (IN / 32);        // 8192
constexpr int G_W2 = (HID / 32) * (HID / 32);       // 16384
constexpr int G_W3 = (NCLS_PAD / 32) * (HID / 32);  // 4096
constexpr int G_X  = (BATCH * IN) / 8192;           // 1024 (32 floats/thread)
constexpr int G_PREP = G_W1 + G_W2 + G_W3 + G_X;

__global__ __launch_bounds__(256)
void prep_all(const float* __restrict__ w1, const float* __restrict__ w2,
              const float* __restrict__ w3, const float* __restrict__ x,
              __half* __restrict__ w1t, __half* __restrict__ w2t,
              __half* __restrict__ w3t, __half* __restrict__ xr) {
    int id = blockIdx.x;
    if (id < G_W1) {
        transpose_job(w1, w1t, IN, HID, id % (HID / 32), id / (HID / 32));
        return;
    }
    id -= G_W1;
    if (id < G_W2) {
        transpose_job(w2, w2t, HID, HID, id % (HID / 32), id / (HID / 32));
        return;
    }
    id -= G_W2;
    if (id < G_W3) {
        transpose_job(w3, w3t, HID, NCLS, id % (NCLS_PAD / 32), id / (NCLS_PAD / 32));
        return;
    }
    id -= G_W3;
    // x: fp16-convert + perm32; 32 floats/thread (one 32-group)
    const size_t base = (size_t)id * 8192 + threadIdx.x * 32;
    float f[32];
#pragma unroll
    for (int i = 0; i < 32; i += 4) *(float4*)&f[i] = *(const float4*)(x + base + i);
    __half h[32];
#pragma unroll
    for (int j = 0; j < 32; j++) h[perm32(j)] = __float2half_rn(f[j]);
#pragma unroll
    for (int i = 0; i < 4; i++)
        *(uint4*)(xr + base + i * 8) = *(uint4*)&h[i * 8];
}

// ----------------------------------------------------------------- launcher
extern "C" void kernel_launch(void* const* d_in, const int* in_sizes, int n_in,
                              void* d_out, int out_size) {
    (void)in_sizes; (void)n_in; (void)out_size;
    const float* x  = (const float*)d_in[0];
    const float* w1 = (const float*)d_in[1];
    const float* b1 = (const float*)d_in[2];
    const float* w2 = (const float*)d_in[3];
    const float* b2 = (const float*)d_in[4];
    const float* w3 = (const float*)d_in[5];
    const float* b3 = (const float*)d_in[6];

    __half *h1, *h2, *xr, *w1t, *w2t, *w3t;
    cudaGetSymbolAddress((void**)&h1,  g_h1);
    cudaGetSymbolAddress((void**)&h2,  g_h2);
    cudaGetSymbolAddress((void**)&xr,  g_xr);
    cudaGetSymbolAddress((void**)&w1t, g_w1t);
    cudaGetSymbolAddress((void**)&w2t, g_w2t);
    cudaGetSymbolAddress((void**)&w3t, g_w3t);

    constexpr int SM256 = STAGES * (A_ST + NSUB * 256 * 32 * 2);  // 196608
    constexpr int SM128 = STAGES * (A_ST + NSUB * 128 * 32 * 2);  // 131072
    cudaFuncSetAttribute(mlp_gemm_h<256>,
                         cudaFuncAttributeMaxDynamicSharedMemorySize, SM256);
    cudaFuncSetAttribute(mlp_gemm_h<128>,
                         cudaFuncAttributeMaxDynamicSharedMemorySize, SM128);

    prep_all<<<G_PREP, 256>>>(w1, w2, w3, x, w1t, w2t, w3t, xr);

    const int MT = BATCH / BM;                     // 32
    const int MAIN = 3 * NSM;                      // 456 tiles = 3 exact waves
    const int REM_T = 512 - MAIN;                  // 56 tiles
    const int REM_U = 2 * REM_T;                   // 112 half-tiles

    // layer 1 (K=2048): main 3 waves + half-width remainder wave
    mlp_gemm_h<256><<<NSM, 256, SM256>>>(
        xr, w1t, b1, h1, IN, HID, MT, MAIN, 0, /*relu|h16*/ 3);
    mlp_gemm_h<128><<<REM_U, 256, SM128>>>(
        xr, w1t, b1, h1, IN, HID, MT, REM_U, MAIN, 3);

    // layer 2 (K=4096)
    mlp_gemm_h<256><<<NSM, 256, SM256>>>(
        h1, w2t, b2, h2, HID, HID, MT, MAIN, 0, 3);
    mlp_gemm_h<128><<<REM_U, 256, SM128>>>(
        h1, w2t, b2, h2, HID, HID, MT, REM_U, MAIN, 3);

    // layer 3 (128 tiles, single wave)
    mlp_gemm_h<256><<<NSM, 256, SM256>>>(
        h2, w3t, b3, d_out, HID, NCLS, MT, 128, 0, 0);
}